// round 13
// baseline (speedup 1.0000x reference)
#include <cuda_runtime.h>
#include <cuda_bf16.h>
#include <cstdint>

#define B_ 4
#define T_ 2048
#define C_ 1024
#define H_ 16
#define HD_ 64
#define QKVC (3 * C_)
#define BT (B_ * T_)

// ---------------- scratch (no cudaMalloc allowed) ----------------
__device__ __nv_bfloat16 g_qkvh[(size_t)BT * QKVC];        // 48 MB
__device__ __nv_bfloat16 g_qkvl[(size_t)BT * QKVC];        // 48 MB
__device__ __nv_bfloat16 g_xh[(size_t)BT * C_];            // act split (x, then attn out)
__device__ __nv_bfloat16 g_xl[(size_t)BT * C_];
__device__ __nv_bfloat16 g_wah[(size_t)QKVC * C_];
__device__ __nv_bfloat16 g_wal[(size_t)QKVC * C_];
__device__ __nv_bfloat16 g_wph[(size_t)C_ * C_];
__device__ __nv_bfloat16 g_wpl[(size_t)C_ * C_];

__device__ __forceinline__ uint32_t smem_u32(const void* p) {
    return (uint32_t)__cvta_generic_to_shared(p);
}

// ---- warp-level tensor core ops (sm_80-era PTX, legal on plain sm_103) ----
#define LDSM_X4(r0, r1, r2, r3, addr) \
    asm volatile("ldmatrix.sync.aligned.m8n8.x4.shared.b16 {%0,%1,%2,%3}, [%4];" \
        : "=r"(r0), "=r"(r1), "=r"(r2), "=r"(r3) : "r"(addr))

#define LDSM_X4_T(r0, r1, r2, r3, addr) \
    asm volatile("ldmatrix.sync.aligned.m8n8.x4.trans.shared.b16 {%0,%1,%2,%3}, [%4];" \
        : "=r"(r0), "=r"(r1), "=r"(r2), "=r"(r3) : "r"(addr))

#define MMA_BF16(D, a0, a1, a2, a3, b0, b1) \
    asm volatile("mma.sync.aligned.m16n8k16.row.col.f32.bf16.bf16.f32 " \
        "{%0,%1,%2,%3}, {%4,%5,%6,%7}, {%8,%9}, {%0,%1,%2,%3};" \
        : "+f"((D)[0]), "+f"((D)[1]), "+f"((D)[2]), "+f"((D)[3]) \
        : "r"(a0), "r"(a1), "r"(a2), "r"(a3), "r"(b0), "r"(b1))

#define CP_ASYNC16(saddr, gptr) \
    asm volatile("cp.async.cg.shared.global [%0], [%1], 16;" \
        :: "r"(saddr), "l"(gptr))
#define CP_COMMIT() asm volatile("cp.async.commit_group;")
#define CP_WAIT(n)  asm volatile("cp.async.wait_group %0;" :: "n"(n))

// ---------------------------------------------------------------------------
// fp32 -> bf16 hi/lo split (elementwise)
// ---------------------------------------------------------------------------
__global__ __launch_bounds__(256) void split_k(const float* __restrict__ in,
                                               __nv_bfloat16* __restrict__ hi,
                                               __nv_bfloat16* __restrict__ lo, int n4)
{
    int idx = blockIdx.x * 256 + threadIdx.x;
    if (idx >= n4) return;
    float4 v = ((const float4*)in)[idx];
    __nv_bfloat16 h0 = __float2bfloat16(v.x), h1 = __float2bfloat16(v.y);
    __nv_bfloat16 h2 = __float2bfloat16(v.z), h3 = __float2bfloat16(v.w);
    __nv_bfloat16 l0 = __float2bfloat16(v.x - __bfloat162float(h0));
    __nv_bfloat16 l1 = __float2bfloat16(v.y - __bfloat162float(h1));
    __nv_bfloat16 l2 = __float2bfloat16(v.z - __bfloat162float(h2));
    __nv_bfloat16 l3 = __float2bfloat16(v.w - __bfloat162float(h3));
    ((__nv_bfloat162*)hi)[idx * 2]     = __nv_bfloat162(h0, h1);
    ((__nv_bfloat162*)hi)[idx * 2 + 1] = __nv_bfloat162(h2, h3);
    ((__nv_bfloat162*)lo)[idx * 2]     = __nv_bfloat162(l0, l1);
    ((__nv_bfloat162*)lo)[idx * 2 + 1] = __nv_bfloat162(l2, l3);
}

// ---------------------------------------------------------------------------
// W[K][N] -> Wt[N][K] bf16 hi/lo split (tiled transpose)
// ---------------------------------------------------------------------------
__global__ __launch_bounds__(256) void tsplit_k(const float* __restrict__ W,
                                                __nv_bfloat16* __restrict__ hi,
                                                __nv_bfloat16* __restrict__ lo,
                                                int K, int N)
{
    __shared__ float t[32][33];
    const int n0 = blockIdx.x * 32, k0 = blockIdx.y * 32;
    const int txi = threadIdx.x, tyi = threadIdx.y;
#pragma unroll
    for (int i = 0; i < 4; i++)
        t[tyi + i * 8][txi] = W[(size_t)(k0 + tyi + i * 8) * N + n0 + txi];
    __syncthreads();
#pragma unroll
    for (int i = 0; i < 4; i++) {
        float v = t[txi][tyi + i * 8];
        __nv_bfloat16 h = __float2bfloat16(v);
        __nv_bfloat16 l = __float2bfloat16(v - __bfloat162float(h));
        size_t o = (size_t)(n0 + tyi + i * 8) * K + k0 + txi;
        hi[o] = h;
        lo[o] = l;
    }
}

// ---------------------------------------------------------------------------
// mma.sync split-bf16 GEMM, 2-stage cp.async (measured core, unchanged).
// SPLIT=1: writes bf16 hi/lo output (Ch/Cl), scaling cols < qscale_n by 0.125.
// SPLIT=0: writes fp32 C.
// ---------------------------------------------------------------------------
#define GBM 128
#define GBN 128
#define GBK 64
#define LROW 144
#define TILE_B (128 * LROW)
#define STG_B  (4 * TILE_B)
#define GEMM_SMEM (2 * STG_B)

template <int SPLIT>
__global__ __launch_bounds__(256) void gemm_mma(
    const __nv_bfloat16* __restrict__ Ah, const __nv_bfloat16* __restrict__ Al,
    const __nv_bfloat16* __restrict__ Bh, const __nv_bfloat16* __restrict__ Bl,
    const float* __restrict__ bias, float* __restrict__ C,
    __nv_bfloat16* __restrict__ Ch, __nv_bfloat16* __restrict__ Cl,
    int qscale_n, int M, int N, int K)
{
    extern __shared__ __align__(128) char sm[];
    const uint32_t sb = smem_u32(sm);
    const int tid = threadIdx.x;
    const int wid = tid >> 5, lane = tid & 31;
    const int wm = wid & 3, wn = wid >> 2;
    const int bm = blockIdx.y * GBM, bn = blockIdx.x * GBN;

    float acc[2][8][4];
#pragma unroll
    for (int mi = 0; mi < 2; mi++)
#pragma unroll
        for (int ni = 0; ni < 8; ni++)
#pragma unroll
            for (int c = 0; c < 4; c++) acc[mi][ni][c] = 0.f;

    const uint32_t aRow = (uint32_t)(wm * 32 + (lane & 15));
    const uint32_t aKb  = (uint32_t)((lane >> 4) * 16);
    const uint32_t bRow = (uint32_t)(wn * 64 + (lane & 7) + ((lane >> 4) << 3));
    const uint32_t bKb  = (uint32_t)(((lane >> 3) & 1) * 16);

    const int KT = K / GBK;

#define LOAD_STAGE(s, k0)                                                      \
    do {                                                                       \
        uint32_t sbase = sb + (uint32_t)(s) * STG_B;                           \
        _Pragma("unroll")                                                      \
        for (int it = 0; it < 4; it++) {                                       \
            int idx = tid + it * 256;                                          \
            int r = idx >> 3, c8 = idx & 7;                                    \
            uint32_t so = (uint32_t)(r * LROW + c8 * 16);                      \
            const __nv_bfloat16* pa = Ah + (size_t)(bm + r) * K + (k0) + c8 * 8; \
            const __nv_bfloat16* pl = Al + (size_t)(bm + r) * K + (k0) + c8 * 8; \
            const __nv_bfloat16* pb = Bh + (size_t)(bn + r) * K + (k0) + c8 * 8; \
            const __nv_bfloat16* pc = Bl + (size_t)(bn + r) * K + (k0) + c8 * 8; \
            CP_ASYNC16(sbase + so, pa);                                        \
            CP_ASYNC16(sbase + TILE_B + so, pl);                               \
            CP_ASYNC16(sbase + 2 * TILE_B + so, pb);                           \
            CP_ASYNC16(sbase + 3 * TILE_B + so, pc);                           \
        }                                                                      \
    } while (0)

    LOAD_STAGE(0, 0);
    CP_COMMIT();

    for (int kt = 0; kt < KT; kt++) {
        if (kt + 1 < KT) {
            LOAD_STAGE((kt + 1) & 1, (kt + 1) * GBK);
            CP_COMMIT();
            CP_WAIT(1);
        } else {
            CP_WAIT(0);
        }
        __syncthreads();

        const uint32_t stg = sb + (uint32_t)(kt & 1) * STG_B;
#pragma unroll
        for (int ks = 0; ks < 4; ks++) {
            uint32_t ah[2][4], al[2][4];
#pragma unroll
            for (int mi = 0; mi < 2; mi++) {
                uint32_t ad = stg + (aRow + mi * 16) * LROW + ks * 32 + aKb;
                LDSM_X4(ah[mi][0], ah[mi][1], ah[mi][2], ah[mi][3], ad);
                LDSM_X4(al[mi][0], al[mi][1], al[mi][2], al[mi][3], ad + TILE_B);
            }
#pragma unroll
            for (int np = 0; np < 4; np++) {
                uint32_t bd = stg + 2 * TILE_B + (bRow + np * 16) * LROW + ks * 32 + bKb;
                uint32_t bh0, bh1, bh2, bh3, bl0, bl1, bl2, bl3;
                LDSM_X4(bh0, bh1, bh2, bh3, bd);
                LDSM_X4(bl0, bl1, bl2, bl3, bd + TILE_B);
#pragma unroll
                for (int mi = 0; mi < 2; mi++) {
                    float* d0 = acc[mi][np * 2];
                    float* d1 = acc[mi][np * 2 + 1];
                    MMA_BF16(d0, ah[mi][0], ah[mi][1], ah[mi][2], ah[mi][3], bh0, bh1);
                    MMA_BF16(d0, al[mi][0], al[mi][1], al[mi][2], al[mi][3], bh0, bh1);
                    MMA_BF16(d0, ah[mi][0], ah[mi][1], ah[mi][2], ah[mi][3], bl0, bl1);
                    MMA_BF16(d1, ah[mi][0], ah[mi][1], ah[mi][2], ah[mi][3], bh2, bh3);
                    MMA_BF16(d1, al[mi][0], al[mi][1], al[mi][2], al[mi][3], bh2, bh3);
                    MMA_BF16(d1, ah[mi][0], ah[mi][1], ah[mi][2], ah[mi][3], bl2, bl3);
                }
            }
        }
        __syncthreads();
    }

    const int gr = lane >> 2, qc = lane & 3;
#pragma unroll
    for (int mi = 0; mi < 2; mi++) {
#pragma unroll
        for (int ni = 0; ni < 8; ni++) {
            int row0 = bm + wm * 32 + mi * 16 + gr;
            int col = bn + wn * 64 + ni * 8 + qc * 2;
            float b0 = bias[col], b1 = bias[col + 1];
            float v00 = acc[mi][ni][0] + b0, v01 = acc[mi][ni][1] + b1;
            float v10 = acc[mi][ni][2] + b0, v11 = acc[mi][ni][3] + b1;
            if (SPLIT) {
                float sc = (col < qscale_n) ? 0.125f : 1.f;
                v00 *= sc; v01 *= sc; v10 *= sc; v11 *= sc;
                __nv_bfloat16 h00 = __float2bfloat16(v00), h01 = __float2bfloat16(v01);
                __nv_bfloat16 h10 = __float2bfloat16(v10), h11 = __float2bfloat16(v11);
                __nv_bfloat16 l00 = __float2bfloat16(v00 - __bfloat162float(h00));
                __nv_bfloat16 l01 = __float2bfloat16(v01 - __bfloat162float(h01));
                __nv_bfloat16 l10 = __float2bfloat16(v10 - __bfloat162float(h10));
                __nv_bfloat16 l11 = __float2bfloat16(v11 - __bfloat162float(h11));
                *(__nv_bfloat162*)(Ch + (size_t)row0 * N + col)       = __nv_bfloat162(h00, h01);
                *(__nv_bfloat162*)(Cl + (size_t)row0 * N + col)       = __nv_bfloat162(l00, l01);
                *(__nv_bfloat162*)(Ch + (size_t)(row0 + 8) * N + col) = __nv_bfloat162(h10, h11);
                *(__nv_bfloat162*)(Cl + (size_t)(row0 + 8) * N + col) = __nv_bfloat162(l10, l11);
            } else {
                float2 w0 = {v00, v01}, w1 = {v10, v11};
                *(float2*)(C + (size_t)row0 * N + col) = w0;
                *(float2*)(C + (size_t)(row0 + 8) * N + col) = w1;
            }
        }
    }
}

// ---------------------------------------------------------------------------
// bf16-split flash attention. Grid (T/128, H, B), 256 threads (8 warps).
// Warp w owns query rows 16w..16w+15. K/V arrive pre-split bf16 from the QKV
// GEMM (Q pre-scaled by 1/8 there). ldmatrix-fed 3-term split MMAs.
// smem (bytes, bf16 rows padded 64->72 elems = 144B):
//   Qh 0 | Ql 18432 | stage0 {Kh,Kl,Vh,Vl} 36864 | stage1 73728
//   Ph 110592 | Pl 129024 | total 147456
// ---------------------------------------------------------------------------
#define AQH 0
#define AQL 18432
#define ASTG0 36864
#define ASTG_SZ 36864
#define AKL_OFF 9216
#define AVH_OFF 18432
#define APH 110592
#define APL 129024
#define ATTN_SMEM 147456

__global__ __launch_bounds__(256) void attn_mma(
    const __nv_bfloat16* __restrict__ qh, const __nv_bfloat16* __restrict__ ql,
    __nv_bfloat16* __restrict__ yh, __nv_bfloat16* __restrict__ yl)
{
    extern __shared__ __align__(128) char sma[];
    const uint32_t sb = smem_u32(sma);
    const int tid = threadIdx.x;
    const int w = tid >> 5, lane = tid & 31;
    const int g = lane >> 2, q = lane & 3;
    const int q0 = blockIdx.x * 128;
    const int h = blockIdx.y;
    const int b = blockIdx.z;
    const size_t bq = (size_t)b * T_ * QKVC;
    const int qoff = h * HD_;
    const int koff = C_ + h * HD_;
    const int voff = 2 * C_ + h * HD_;

    // K/V stage: t 0=Kh 1=Kl 2=Vh 3=Vl, 64 rows x 8 16B-chunks each
#define KV_LOAD(s, t0)                                                         \
    do {                                                                       \
        uint32_t stg_ = sb + ASTG0 + (uint32_t)(s) * ASTG_SZ;                  \
        _Pragma("unroll")                                                      \
        for (int j = 0; j < 8; j++) {                                          \
            int id = tid + j * 256;                                            \
            int t = id >> 9, rem = id & 511, r = rem >> 3, c = rem & 7;        \
            int off = (t & 2) ? voff : koff;                                   \
            const __nv_bfloat16* sp = ((t & 1) ? ql : qh) + bq +               \
                (size_t)((t0) + r) * QKVC + off + c * 8;                       \
            CP_ASYNC16(stg_ + (uint32_t)(t * 9216 + r * 144 + c * 16), sp);    \
        }                                                                      \
    } while (0)

    // prologue: Q (both halves) + first K/V stage in one group
#pragma unroll
    for (int j = 0; j < 8; j++) {
        int id = tid + j * 256;
        int t = id >> 10, rem = id & 1023, r = rem >> 3, c = rem & 7;
        const __nv_bfloat16* sp = (t ? ql : qh) + bq +
            (size_t)(q0 + r) * QKVC + qoff + c * 8;
        CP_ASYNC16(sb + (uint32_t)(t * 18432 + r * 144 + c * 16), sp);
    }
    KV_LOAD(0, 0);
    CP_COMMIT();

    uint32_t Qh[4][4], Qlr[4][4];
    float m0 = -1e30f, m1 = -1e30f, l0 = 0.f, l1 = 0.f;
    float o[8][4];
#pragma unroll
    for (int nt = 0; nt < 8; nt++)
#pragma unroll
        for (int c = 0; c < 4; c++) o[nt][c] = 0.f;

    const uint32_t aoff = (uint32_t)((16 * w + (lane & 15)) * 144 + (lane >> 4) * 16);
    const uint32_t bRow = (uint32_t)((lane & 7) + ((lane >> 4) << 3));
    const uint32_t bKb  = (uint32_t)(((lane >> 3) & 1) * 16);
    const uint32_t vRow = (uint32_t)((lane & 7) + (((lane >> 3) & 1) << 3));
    const uint32_t vC16 = (uint32_t)((lane >> 4) * 16);

    for (int kt = 0; kt < T_ / 64; kt++) {
        if (kt + 1 < T_ / 64) {
            KV_LOAD((kt + 1) & 1, (kt + 1) * 64);
            CP_COMMIT();
            CP_WAIT(1);
        } else {
            CP_WAIT(0);
        }
        __syncthreads();

        if (kt == 0) {   // Q fragments -> registers, once
#pragma unroll
            for (int kb = 0; kb < 4; kb++) {
                LDSM_X4(Qh[kb][0], Qh[kb][1], Qh[kb][2], Qh[kb][3],
                        sb + AQH + aoff + kb * 32);
                LDSM_X4(Qlr[kb][0], Qlr[kb][1], Qlr[kb][2], Qlr[kb][3],
                        sb + AQL + aoff + kb * 32);
            }
        }

        const uint32_t stg = sb + ASTG0 + (uint32_t)(kt & 1) * ASTG_SZ;

        // S = Q K^T (3-term bf16 split)
        float s[8][4];
#pragma unroll
        for (int nt = 0; nt < 8; nt++)
#pragma unroll
            for (int c = 0; c < 4; c++) s[nt][c] = 0.f;

#pragma unroll
        for (int kb = 0; kb < 4; kb++) {
#pragma unroll
            for (int np = 0; np < 4; np++) {
                uint32_t kd = stg + (np * 16 + bRow) * 144 + kb * 32 + bKb;
                uint32_t kh0, kh1, kh2, kh3, kl0, kl1, kl2, kl3;
                LDSM_X4(kh0, kh1, kh2, kh3, kd);
                LDSM_X4(kl0, kl1, kl2, kl3, kd + AKL_OFF);
                float* d0 = s[np * 2];
                float* d1 = s[np * 2 + 1];
                MMA_BF16(d0, Qh[kb][0], Qh[kb][1], Qh[kb][2], Qh[kb][3], kh0, kh1);
                MMA_BF16(d0, Qlr[kb][0], Qlr[kb][1], Qlr[kb][2], Qlr[kb][3], kh0, kh1);
                MMA_BF16(d0, Qh[kb][0], Qh[kb][1], Qh[kb][2], Qh[kb][3], kl0, kl1);
                MMA_BF16(d1, Qh[kb][0], Qh[kb][1], Qh[kb][2], Qh[kb][3], kh2, kh3);
                MMA_BF16(d1, Qlr[kb][0], Qlr[kb][1], Qlr[kb][2], Qlr[kb][3], kh2, kh3);
                MMA_BF16(d1, Qh[kb][0], Qh[kb][1], Qh[kb][2], Qh[kb][3], kl2, kl3);
            }
        }

        // online softmax (rows g / g+8, warp-local across lanes 4g..4g+3)
        float mt0 = -1e30f, mt1 = -1e30f;
#pragma unroll
        for (int nt = 0; nt < 8; nt++) {
            mt0 = fmaxf(mt0, fmaxf(s[nt][0], s[nt][1]));
            mt1 = fmaxf(mt1, fmaxf(s[nt][2], s[nt][3]));
        }
#pragma unroll
        for (int off = 1; off <= 2; off <<= 1) {
            mt0 = fmaxf(mt0, __shfl_xor_sync(0xffffffffu, mt0, off));
            mt1 = fmaxf(mt1, __shfl_xor_sync(0xffffffffu, mt1, off));
        }
        float mn0 = fmaxf(m0, mt0), mn1 = fmaxf(m1, mt1);
        float al0 = __expf(m0 - mn0), al1 = __expf(m1 - mn1);
        m0 = mn0;
        m1 = mn1;

        // exp, accumulate l, stage P as bf16 hi/lo
        const uint32_t p0a = sb + APH + (uint32_t)((16 * w + g) * 144 + q * 4);
        float lt0 = 0.f, lt1 = 0.f;
#pragma unroll
        for (int nt = 0; nt < 8; nt++) {
            float p0 = __expf(s[nt][0] - mn0);
            float p1 = __expf(s[nt][1] - mn0);
            float p2 = __expf(s[nt][2] - mn1);
            float p3 = __expf(s[nt][3] - mn1);
            lt0 += p0 + p1;
            lt1 += p2 + p3;
            __nv_bfloat16 h0 = __float2bfloat16(p0), h1 = __float2bfloat16(p1);
            __nv_bfloat16 h2 = __float2bfloat16(p2), h3 = __float2bfloat16(p3);
            __nv_bfloat16 e0 = __float2bfloat16(p0 - __bfloat162float(h0));
            __nv_bfloat16 e1 = __float2bfloat16(p1 - __bfloat162float(h1));
            __nv_bfloat16 e2 = __float2bfloat16(p2 - __bfloat162float(h2));
            __nv_bfloat16 e3 = __float2bfloat16(p3 - __bfloat162float(h3));
            uint32_t rowg = p0a + nt * 16;
            asm volatile("st.shared.b32 [%0], %1;" :: "r"(rowg),
                         "r"(__float_as_uint(0) | (uint32_t)(__bfloat16_as_ushort(h0)) |
                             ((uint32_t)__bfloat16_as_ushort(h1) << 16)) : "memory");
            asm volatile("st.shared.b32 [%0], %1;" :: "r"(rowg + 8 * 144),
                         "r"((uint32_t)(__bfloat16_as_ushort(h2)) |
                             ((uint32_t)__bfloat16_as_ushort(h3) << 16)) : "memory");
            asm volatile("st.shared.b32 [%0], %1;" :: "r"(rowg + (APL - APH)),
                         "r"((uint32_t)(__bfloat16_as_ushort(e0)) |
                             ((uint32_t)__bfloat16_as_ushort(e1) << 16)) : "memory");
            asm volatile("st.shared.b32 [%0], %1;" :: "r"(rowg + (APL - APH) + 8 * 144),
                         "r"((uint32_t)(__bfloat16_as_ushort(e2)) |
                             ((uint32_t)__bfloat16_as_ushort(e3) << 16)) : "memory");
        }
#pragma unroll
        for (int off = 1; off <= 2; off <<= 1) {
            lt0 += __shfl_xor_sync(0xffffffffu, lt0, off);
            lt1 += __shfl_xor_sync(0xffffffffu, lt1, off);
        }
        l0 = l0 * al0 + lt0;
        l1 = l1 * al1 + lt1;

#pragma unroll
        for (int nt = 0; nt < 8; nt++) {
            o[nt][0] *= al0;
            o[nt][1] *= al0;
            o[nt][2] *= al1;
            o[nt][3] *= al1;
        }
        __syncwarp();   // P rows are warp-private (stores -> ldmatrix)

        // O += P V (3-term bf16 split; V via trans ldmatrix)
#pragma unroll
        for (int kb = 0; kb < 4; kb++) {
            uint32_t ph[4], pl[4];
            LDSM_X4(ph[0], ph[1], ph[2], ph[3], sb + APH + aoff + kb * 32);
            LDSM_X4(pl[0], pl[1], pl[2], pl[3], sb + APL + aoff + kb * 32);
#pragma unroll
            for (int ng = 0; ng < 4; ng++) {
                uint32_t vd = stg + AVH_OFF + (kb * 16 + vRow) * 144 + ng * 32 + vC16;
                uint32_t vh0, vh1, vh2, vh3, vl0, vl1, vl2, vl3;
                LDSM_X4_T(vh0, vh1, vh2, vh3, vd);
                LDSM_X4_T(vl0, vl1, vl2, vl3, vd + AKL_OFF);
                float* d0 = o[ng * 2];
                float* d1 = o[ng * 2 + 1];
                MMA_BF16(d0, ph[0], ph[1], ph[2], ph[3], vh0, vh1);
                MMA_BF16(d0, pl[0], pl[1], pl[2], pl[3], vh0, vh1);
                MMA_BF16(d0, ph[0], ph[1], ph[2], ph[3], vl0, vl1);
                MMA_BF16(d1, ph[0], ph[1], ph[2], ph[3], vh2, vh3);
                MMA_BF16(d1, pl[0], pl[1], pl[2], pl[3], vh2, vh3);
                MMA_BF16(d1, ph[0], ph[1], ph[2], ph[3], vl2, vl3);
            }
        }
        __syncthreads();   // stage reuse 2 iters later
    }

    // normalize + fused bf16 hi/lo split store
    const float inv0 = 1.f / l0, inv1 = 1.f / l1;
    const int r0 = b * T_ + q0 + 16 * w + g;
#pragma unroll
    for (int nt = 0; nt < 8; nt++) {
        int col = h * HD_ + nt * 8 + 2 * q;
        float v00 = o[nt][0] * inv0, v01 = o[nt][1] * inv0;
        float v10 = o[nt][2] * inv1, v11 = o[nt][3] * inv1;
        __nv_bfloat16 h00 = __float2bfloat16(v00), h01 = __float2bfloat16(v01);
        __nv_bfloat16 h10 = __float2bfloat16(v10), h11 = __float2bfloat16(v11);
        __nv_bfloat16 l00 = __float2bfloat16(v00 - __bfloat162float(h00));
        __nv_bfloat16 l01 = __float2bfloat16(v01 - __bfloat162float(h01));
        __nv_bfloat16 l10 = __float2bfloat16(v10 - __bfloat162float(h10));
        __nv_bfloat16 l11 = __float2bfloat16(v11 - __bfloat162float(h11));
        *(__nv_bfloat162*)(yh + (size_t)r0 * C_ + col)       = __nv_bfloat162(h00, h01);
        *(__nv_bfloat162*)(yl + (size_t)r0 * C_ + col)       = __nv_bfloat162(l00, l01);
        *(__nv_bfloat162*)(yh + (size_t)(r0 + 8) * C_ + col) = __nv_bfloat162(h10, h11);
        *(__nv_bfloat162*)(yl + (size_t)(r0 + 8) * C_ + col) = __nv_bfloat162(l10, l11);
    }
}

extern "C" void kernel_launch(void* const* d_in, const int* in_sizes, int n_in,
                              void* d_out, int out_size)
{
    (void)in_sizes; (void)n_in; (void)out_size;
    const float* x      = (const float*)d_in[0];
    const float* W_attn = (const float*)d_in[1];
    const float* b_attn = (const float*)d_in[2];
    const float* W_proj = (const float*)d_in[3];
    const float* b_proj = (const float*)d_in[4];
    float* out = (float*)d_out;

    __nv_bfloat16 *qkvh, *qkvl, *xh, *xl, *wah, *wal, *wph, *wpl;
    cudaGetSymbolAddress((void**)&qkvh, g_qkvh);
    cudaGetSymbolAddress((void**)&qkvl, g_qkvl);
    cudaGetSymbolAddress((void**)&xh, g_xh);
    cudaGetSymbolAddress((void**)&xl, g_xl);
    cudaGetSymbolAddress((void**)&wah, g_wah);
    cudaGetSymbolAddress((void**)&wal, g_wal);
    cudaGetSymbolAddress((void**)&wph, g_wph);
    cudaGetSymbolAddress((void**)&wpl, g_wpl);

    cudaFuncSetAttribute(attn_mma, cudaFuncAttributeMaxDynamicSharedMemorySize, ATTN_SMEM);
    cudaFuncSetAttribute(gemm_mma<0>, cudaFuncAttributeMaxDynamicSharedMemorySize, GEMM_SMEM);
    cudaFuncSetAttribute(gemm_mma<1>, cudaFuncAttributeMaxDynamicSharedMemorySize, GEMM_SMEM);

    const int n4x = (BT * C_) / 4;

    split_k<<<(n4x + 255) / 256, 256>>>(x, xh, xl, n4x);
    tsplit_k<<<dim3(QKVC / 32, C_ / 32), dim3(32, 8)>>>(W_attn, wah, wal, C_, QKVC);
    tsplit_k<<<dim3(C_ / 32, C_ / 32), dim3(32, 8)>>>(W_proj, wph, wpl, C_, C_);

    // 1) qkv (bf16 hi/lo, Q cols pre-scaled by 1/8)
    gemm_mma<1><<<dim3(QKVC / GBN, BT / GBM), 256, GEMM_SMEM>>>(
        xh, xl, wah, wal, b_attn, nullptr, qkvh, qkvl, C_, BT, QKVC, C_);

    // 2) SDPA (bf16-split HMMA flash), writes split y into xh/xl
    attn_mma<<<dim3(T_ / 128, H_, B_), 256, ATTN_SMEM>>>(qkvh, qkvl, xh, xl);

    // 3) out = y @ W_proj + b_proj (fp32 out)
    gemm_mma<0><<<dim3(C_ / GBN, BT / GBM), 256, GEMM_SMEM>>>(
        xh, xl, wph, wpl, b_proj, out, nullptr, nullptr, 0, BT, C_, C_);
}

// round 14
// speedup vs baseline: 1.1109x; 1.1109x over previous
#include <cuda_runtime.h>
#include <cuda_bf16.h>
#include <cstdint>

#define B_ 4
#define T_ 2048
#define C_ 1024
#define H_ 16
#define HD_ 64
#define QKVC (3 * C_)
#define BT (B_ * T_)

// ---------------- scratch (no cudaMalloc allowed) ----------------
__device__ __nv_bfloat16 g_qkvh[(size_t)BT * QKVC];
__device__ __nv_bfloat16 g_qkvl[(size_t)BT * QKVC];
__device__ __nv_bfloat16 g_xh[(size_t)BT * C_];
__device__ __nv_bfloat16 g_xl[(size_t)BT * C_];
__device__ __nv_bfloat16 g_wah[(size_t)QKVC * C_];
__device__ __nv_bfloat16 g_wal[(size_t)QKVC * C_];
__device__ __nv_bfloat16 g_wph[(size_t)C_ * C_];
__device__ __nv_bfloat16 g_wpl[(size_t)C_ * C_];

__device__ __forceinline__ uint32_t smem_u32(const void* p) {
    return (uint32_t)__cvta_generic_to_shared(p);
}

#define LDSM_X4(r0, r1, r2, r3, addr) \
    asm volatile("ldmatrix.sync.aligned.m8n8.x4.shared.b16 {%0,%1,%2,%3}, [%4];" \
        : "=r"(r0), "=r"(r1), "=r"(r2), "=r"(r3) : "r"(addr))

#define LDSM_X4_T(r0, r1, r2, r3, addr) \
    asm volatile("ldmatrix.sync.aligned.m8n8.x4.trans.shared.b16 {%0,%1,%2,%3}, [%4];" \
        : "=r"(r0), "=r"(r1), "=r"(r2), "=r"(r3) : "r"(addr))

#define MMA_BF16(D, a0, a1, a2, a3, b0, b1) \
    asm volatile("mma.sync.aligned.m16n8k16.row.col.f32.bf16.bf16.f32 " \
        "{%0,%1,%2,%3}, {%4,%5,%6,%7}, {%8,%9}, {%0,%1,%2,%3};" \
        : "+f"((D)[0]), "+f"((D)[1]), "+f"((D)[2]), "+f"((D)[3]) \
        : "r"(a0), "r"(a1), "r"(a2), "r"(a3), "r"(b0), "r"(b1))

#define CP_ASYNC16(saddr, gptr) \
    asm volatile("cp.async.cg.shared.global [%0], [%1], 16;" \
        :: "r"(saddr), "l"(gptr))
#define CP_COMMIT() asm volatile("cp.async.commit_group;")
#define CP_WAIT(n)  asm volatile("cp.async.wait_group %0;" :: "n"(n))

// ---------------------------------------------------------------------------
// fp32 -> bf16 hi/lo split (elementwise)
// ---------------------------------------------------------------------------
__global__ __launch_bounds__(256) void split_k(const float* __restrict__ in,
                                               __nv_bfloat16* __restrict__ hi,
                                               __nv_bfloat16* __restrict__ lo, int n4)
{
    int idx = blockIdx.x * 256 + threadIdx.x;
    if (idx >= n4) return;
    float4 v = ((const float4*)in)[idx];
    __nv_bfloat16 h0 = __float2bfloat16(v.x), h1 = __float2bfloat16(v.y);
    __nv_bfloat16 h2 = __float2bfloat16(v.z), h3 = __float2bfloat16(v.w);
    __nv_bfloat16 l0 = __float2bfloat16(v.x - __bfloat162float(h0));
    __nv_bfloat16 l1 = __float2bfloat16(v.y - __bfloat162float(h1));
    __nv_bfloat16 l2 = __float2bfloat16(v.z - __bfloat162float(h2));
    __nv_bfloat16 l3 = __float2bfloat16(v.w - __bfloat162float(h3));
    ((__nv_bfloat162*)hi)[idx * 2]     = __nv_bfloat162(h0, h1);
    ((__nv_bfloat162*)hi)[idx * 2 + 1] = __nv_bfloat162(h2, h3);
    ((__nv_bfloat162*)lo)[idx * 2]     = __nv_bfloat162(l0, l1);
    ((__nv_bfloat162*)lo)[idx * 2 + 1] = __nv_bfloat162(l2, l3);
}

// ---------------------------------------------------------------------------
// W[K][N] -> Wt[N][K] bf16 hi/lo split (tiled transpose)
// ---------------------------------------------------------------------------
__global__ __launch_bounds__(256) void tsplit_k(const float* __restrict__ W,
                                                __nv_bfloat16* __restrict__ hi,
                                                __nv_bfloat16* __restrict__ lo,
                                                int K, int N)
{
    __shared__ float t[32][33];
    const int n0 = blockIdx.x * 32, k0 = blockIdx.y * 32;
    const int txi = threadIdx.x, tyi = threadIdx.y;
#pragma unroll
    for (int i = 0; i < 4; i++)
        t[tyi + i * 8][txi] = W[(size_t)(k0 + tyi + i * 8) * N + n0 + txi];
    __syncthreads();
#pragma unroll
    for (int i = 0; i < 4; i++) {
        float v = t[txi][tyi + i * 8];
        __nv_bfloat16 h = __float2bfloat16(v);
        __nv_bfloat16 l = __float2bfloat16(v - __bfloat162float(h));
        size_t o = (size_t)(n0 + tyi + i * 8) * K + k0 + txi;
        hi[o] = h;
        lo[o] = l;
    }
}

// ---------------------------------------------------------------------------
// mma.sync split-bf16 GEMM, CTA 256x128, BK=64, 8 warps (4m x 2n), warp 64x64.
// 2-stage cp.async. SPLIT=1 writes bf16 hi/lo (cols<qscale_n scaled 0.125).
// smem/stage: Ah 36864 | Al 36864 | Bh 18432 | Bl 18432 = 110592; x2 stages.
// ---------------------------------------------------------------------------
#define GBM 256
#define GBN 128
#define GBK 64
#define LROW 144
#define TILE_A (256 * LROW)        // 36864
#define TILE_BT (128 * LROW)       // 18432
#define G_AL TILE_A
#define G_BH (2 * TILE_A)
#define G_BL (2 * TILE_A + TILE_BT)
#define STG_B  (2 * TILE_A + 2 * TILE_BT)   // 110592
#define GEMM_SMEM (2 * STG_B)               // 221184

template <int SPLIT>
__global__ __launch_bounds__(256) void gemm_mma(
    const __nv_bfloat16* __restrict__ Ah, const __nv_bfloat16* __restrict__ Al,
    const __nv_bfloat16* __restrict__ Bh, const __nv_bfloat16* __restrict__ Bl,
    const float* __restrict__ bias, float* __restrict__ C,
    __nv_bfloat16* __restrict__ Ch, __nv_bfloat16* __restrict__ Cl,
    int qscale_n, int M, int N, int K)
{
    extern __shared__ __align__(128) char sm[];
    const uint32_t sb = smem_u32(sm);
    const int tid = threadIdx.x;
    const int wid = tid >> 5, lane = tid & 31;
    const int wm = wid & 3, wn = wid >> 2;
    const int bm = blockIdx.y * GBM, bn = blockIdx.x * GBN;

    float acc[4][8][4];
#pragma unroll
    for (int mi = 0; mi < 4; mi++)
#pragma unroll
        for (int ni = 0; ni < 8; ni++)
#pragma unroll
            for (int c = 0; c < 4; c++) acc[mi][ni][c] = 0.f;

    const uint32_t aRow = (uint32_t)(wm * 64 + (lane & 15));
    const uint32_t aKb  = (uint32_t)((lane >> 4) * 16);
    const uint32_t bRow = (uint32_t)(wn * 64 + (lane & 7) + ((lane >> 4) << 3));
    const uint32_t bKb  = (uint32_t)(((lane >> 3) & 1) * 16);

    const int KT = K / GBK;

#define LOAD_STAGE(s, k0)                                                      \
    do {                                                                       \
        uint32_t sbase = sb + (uint32_t)(s) * STG_B;                           \
        _Pragma("unroll")                                                      \
        for (int it = 0; it < 8; it++) {                                       \
            int idx = tid + it * 256;                                          \
            int r = idx >> 3, c8 = idx & 7;                                    \
            uint32_t so = (uint32_t)(r * LROW + c8 * 16);                      \
            const __nv_bfloat16* pa = Ah + (size_t)(bm + r) * K + (k0) + c8 * 8; \
            const __nv_bfloat16* pl = Al + (size_t)(bm + r) * K + (k0) + c8 * 8; \
            CP_ASYNC16(sbase + so, pa);                                        \
            CP_ASYNC16(sbase + G_AL + so, pl);                                 \
        }                                                                      \
        _Pragma("unroll")                                                      \
        for (int it = 0; it < 4; it++) {                                       \
            int idx = tid + it * 256;                                          \
            int r = idx >> 3, c8 = idx & 7;                                    \
            uint32_t so = (uint32_t)(r * LROW + c8 * 16);                      \
            const __nv_bfloat16* pb = Bh + (size_t)(bn + r) * K + (k0) + c8 * 8; \
            const __nv_bfloat16* pc = Bl + (size_t)(bn + r) * K + (k0) + c8 * 8; \
            CP_ASYNC16(sbase + G_BH + so, pb);                                 \
            CP_ASYNC16(sbase + G_BL + so, pc);                                 \
        }                                                                      \
    } while (0)

    LOAD_STAGE(0, 0);
    CP_COMMIT();

    for (int kt = 0; kt < KT; kt++) {
        if (kt + 1 < KT) {
            LOAD_STAGE((kt + 1) & 1, (kt + 1) * GBK);
            CP_COMMIT();
            CP_WAIT(1);
        } else {
            CP_WAIT(0);
        }
        __syncthreads();

        const uint32_t stg = sb + (uint32_t)(kt & 1) * STG_B;
#pragma unroll
        for (int ks = 0; ks < 4; ks++) {
            uint32_t ah[4][4], al[4][4];
#pragma unroll
            for (int mi = 0; mi < 4; mi++) {
                uint32_t ad = stg + (aRow + mi * 16) * LROW + ks * 32 + aKb;
                LDSM_X4(ah[mi][0], ah[mi][1], ah[mi][2], ah[mi][3], ad);
                LDSM_X4(al[mi][0], al[mi][1], al[mi][2], al[mi][3], ad + G_AL);
            }
#pragma unroll
            for (int np = 0; np < 4; np++) {
                uint32_t bd = stg + G_BH + (bRow + np * 16) * LROW + ks * 32 + bKb;
                uint32_t bh0, bh1, bh2, bh3, bl0, bl1, bl2, bl3;
                LDSM_X4(bh0, bh1, bh2, bh3, bd);
                LDSM_X4(bl0, bl1, bl2, bl3, bd + TILE_BT);
#pragma unroll
                for (int mi = 0; mi < 4; mi++) {
                    float* d0 = acc[mi][np * 2];
                    float* d1 = acc[mi][np * 2 + 1];
                    MMA_BF16(d0, ah[mi][0], ah[mi][1], ah[mi][2], ah[mi][3], bh0, bh1);
                    MMA_BF16(d0, al[mi][0], al[mi][1], al[mi][2], al[mi][3], bh0, bh1);
                    MMA_BF16(d0, ah[mi][0], ah[mi][1], ah[mi][2], ah[mi][3], bl0, bl1);
                    MMA_BF16(d1, ah[mi][0], ah[mi][1], ah[mi][2], ah[mi][3], bh2, bh3);
                    MMA_BF16(d1, al[mi][0], al[mi][1], al[mi][2], al[mi][3], bh2, bh3);
                    MMA_BF16(d1, ah[mi][0], ah[mi][1], ah[mi][2], ah[mi][3], bl2, bl3);
                }
            }
        }
        __syncthreads();
    }

    const int gr = lane >> 2, qc = lane & 3;
#pragma unroll
    for (int mi = 0; mi < 4; mi++) {
#pragma unroll
        for (int ni = 0; ni < 8; ni++) {
            int row0 = bm + wm * 64 + mi * 16 + gr;
            int col = bn + wn * 64 + ni * 8 + qc * 2;
            float b0 = bias[col], b1 = bias[col + 1];
            float v00 = acc[mi][ni][0] + b0, v01 = acc[mi][ni][1] + b1;
            float v10 = acc[mi][ni][2] + b0, v11 = acc[mi][ni][3] + b1;
            if (SPLIT) {
                float sc = (col < qscale_n) ? 0.125f : 1.f;
                v00 *= sc; v01 *= sc; v10 *= sc; v11 *= sc;
                __nv_bfloat16 h00 = __float2bfloat16(v00), h01 = __float2bfloat16(v01);
                __nv_bfloat16 h10 = __float2bfloat16(v10), h11 = __float2bfloat16(v11);
                __nv_bfloat16 l00 = __float2bfloat16(v00 - __bfloat162float(h00));
                __nv_bfloat16 l01 = __float2bfloat16(v01 - __bfloat162float(h01));
                __nv_bfloat16 l10 = __float2bfloat16(v10 - __bfloat162float(h10));
                __nv_bfloat16 l11 = __float2bfloat16(v11 - __bfloat162float(h11));
                *(__nv_bfloat162*)(Ch + (size_t)row0 * N + col)       = __nv_bfloat162(h00, h01);
                *(__nv_bfloat162*)(Cl + (size_t)row0 * N + col)       = __nv_bfloat162(l00, l01);
                *(__nv_bfloat162*)(Ch + (size_t)(row0 + 8) * N + col) = __nv_bfloat162(h10, h11);
                *(__nv_bfloat162*)(Cl + (size_t)(row0 + 8) * N + col) = __nv_bfloat162(l10, l11);
            } else {
                float2 w0 = {v00, v01}, w1 = {v10, v11};
                *(float2*)(C + (size_t)row0 * N + col) = w0;
                *(float2*)(C + (size_t)(row0 + 8) * N + col) = w1;
            }
        }
    }
}

// ---------------------------------------------------------------------------
// bf16-split flash attention. Grid (T/128, H, B), 256 threads (8 warps).
// P overlays Q smem (Q is register-resident after iter 0; both warp-private).
// smem: Qh/Ph 0 | Ql/Pl 18432 | stage0 36864 | stage1 73728 = 110592
// -> 2 CTAs/SM.
// ---------------------------------------------------------------------------
#define AQH 0
#define AQL 18432
#define ASTG0 36864
#define ASTG_SZ 36864
#define AKL_OFF 9216
#define AVH_OFF 18432
#define ATTN_SMEM 110592

__global__ __launch_bounds__(256, 2) void attn_mma(
    const __nv_bfloat16* __restrict__ qh, const __nv_bfloat16* __restrict__ ql,
    __nv_bfloat16* __restrict__ yh, __nv_bfloat16* __restrict__ yl)
{
    extern __shared__ __align__(128) char sma[];
    const uint32_t sb = smem_u32(sma);
    const int tid = threadIdx.x;
    const int w = tid >> 5, lane = tid & 31;
    const int g = lane >> 2, q = lane & 3;
    const int q0 = blockIdx.x * 128;
    const int h = blockIdx.y;
    const int b = blockIdx.z;
    const size_t bq = (size_t)b * T_ * QKVC;
    const int qoff = h * HD_;
    const int koff = C_ + h * HD_;
    const int voff = 2 * C_ + h * HD_;

#define KV_LOAD(s, t0)                                                         \
    do {                                                                       \
        uint32_t stg_ = sb + ASTG0 + (uint32_t)(s) * ASTG_SZ;                  \
        _Pragma("unroll")                                                      \
        for (int j = 0; j < 8; j++) {                                          \
            int id = tid + j * 256;                                            \
            int t = id >> 9, rem = id & 511, r = rem >> 3, c = rem & 7;        \
            int off = (t & 2) ? voff : koff;                                   \
            const __nv_bfloat16* sp = ((t & 1) ? ql : qh) + bq +               \
                (size_t)((t0) + r) * QKVC + off + c * 8;                       \
            CP_ASYNC16(stg_ + (uint32_t)(t * 9216 + r * 144 + c * 16), sp);    \
        }                                                                      \
    } while (0)

    // prologue: Q (both halves) + first K/V stage in one group
#pragma unroll
    for (int j = 0; j < 8; j++) {
        int id = tid + j * 256;
        int t = id >> 10, rem = id & 1023, r = rem >> 3, c = rem & 7;
        const __nv_bfloat16* sp = (t ? ql : qh) + bq +
            (size_t)(q0 + r) * QKVC + qoff + c * 8;
        CP_ASYNC16(sb + (uint32_t)(t * 18432 + r * 144 + c * 16), sp);
    }
    KV_LOAD(0, 0);
    CP_COMMIT();

    uint32_t Qh[4][4], Qlr[4][4];
    float m0 = -1e30f, m1 = -1e30f, l0 = 0.f, l1 = 0.f;
    float o[8][4];
#pragma unroll
    for (int nt = 0; nt < 8; nt++)
#pragma unroll
        for (int c = 0; c < 4; c++) o[nt][c] = 0.f;

    const uint32_t aoff = (uint32_t)((16 * w + (lane & 15)) * 144 + (lane >> 4) * 16);
    const uint32_t bRow = (uint32_t)((lane & 7) + ((lane >> 4) << 3));
    const uint32_t bKb  = (uint32_t)(((lane >> 3) & 1) * 16);
    const uint32_t vRow = (uint32_t)((lane & 7) + (((lane >> 3) & 1) << 3));
    const uint32_t vC16 = (uint32_t)((lane >> 4) * 16);

    for (int kt = 0; kt < T_ / 64; kt++) {
        if (kt + 1 < T_ / 64) {
            KV_LOAD((kt + 1) & 1, (kt + 1) * 64);
            CP_COMMIT();
            CP_WAIT(1);
        } else {
            CP_WAIT(0);
        }
        __syncthreads();

        if (kt == 0) {   // Q fragments -> registers, once (before P overwrites)
#pragma unroll
            for (int kb = 0; kb < 4; kb++) {
                LDSM_X4(Qh[kb][0], Qh[kb][1], Qh[kb][2], Qh[kb][3],
                        sb + AQH + aoff + kb * 32);
                LDSM_X4(Qlr[kb][0], Qlr[kb][1], Qlr[kb][2], Qlr[kb][3],
                        sb + AQL + aoff + kb * 32);
            }
        }

        const uint32_t stg = sb + ASTG0 + (uint32_t)(kt & 1) * ASTG_SZ;

        // S = Q K^T (3-term bf16 split)
        float s[8][4];
#pragma unroll
        for (int nt = 0; nt < 8; nt++)
#pragma unroll
            for (int c = 0; c < 4; c++) s[nt][c] = 0.f;

#pragma unroll
        for (int kb = 0; kb < 4; kb++) {
#pragma unroll
            for (int np = 0; np < 4; np++) {
                uint32_t kd = stg + (np * 16 + bRow) * 144 + kb * 32 + bKb;
                uint32_t kh0, kh1, kh2, kh3, kl0, kl1, kl2, kl3;
                LDSM_X4(kh0, kh1, kh2, kh3, kd);
                LDSM_X4(kl0, kl1, kl2, kl3, kd + AKL_OFF);
                float* d0 = s[np * 2];
                float* d1 = s[np * 2 + 1];
                MMA_BF16(d0, Qh[kb][0], Qh[kb][1], Qh[kb][2], Qh[kb][3], kh0, kh1);
                MMA_BF16(d0, Qlr[kb][0], Qlr[kb][1], Qlr[kb][2], Qlr[kb][3], kh0, kh1);
                MMA_BF16(d0, Qh[kb][0], Qh[kb][1], Qh[kb][2], Qh[kb][3], kl0, kl1);
                MMA_BF16(d1, Qh[kb][0], Qh[kb][1], Qh[kb][2], Qh[kb][3], kh2, kh3);
                MMA_BF16(d1, Qlr[kb][0], Qlr[kb][1], Qlr[kb][2], Qlr[kb][3], kh2, kh3);
                MMA_BF16(d1, Qh[kb][0], Qh[kb][1], Qh[kb][2], Qh[kb][3], kl2, kl3);
            }
        }

        // online softmax (rows g / g+8, warp-local across lanes 4g..4g+3)
        float mt0 = -1e30f, mt1 = -1e30f;
#pragma unroll
        for (int nt = 0; nt < 8; nt++) {
            mt0 = fmaxf(mt0, fmaxf(s[nt][0], s[nt][1]));
            mt1 = fmaxf(mt1, fmaxf(s[nt][2], s[nt][3]));
        }
#pragma unroll
        for (int off = 1; off <= 2; off <<= 1) {
            mt0 = fmaxf(mt0, __shfl_xor_sync(0xffffffffu, mt0, off));
            mt1 = fmaxf(mt1, __shfl_xor_sync(0xffffffffu, mt1, off));
        }
        float mn0 = fmaxf(m0, mt0), mn1 = fmaxf(m1, mt1);
        float al0 = __expf(m0 - mn0), al1 = __expf(m1 - mn1);
        m0 = mn0;
        m1 = mn1;

        // exp, accumulate l, stage P (bf16 hi/lo) into the Q smem region
        const uint32_t p0a = sb + AQH + (uint32_t)((16 * w + g) * 144 + q * 4);
        float lt0 = 0.f, lt1 = 0.f;
#pragma unroll
        for (int nt = 0; nt < 8; nt++) {
            float p0 = __expf(s[nt][0] - mn0);
            float p1 = __expf(s[nt][1] - mn0);
            float p2 = __expf(s[nt][2] - mn1);
            float p3 = __expf(s[nt][3] - mn1);
            lt0 += p0 + p1;
            lt1 += p2 + p3;
            __nv_bfloat16 h0 = __float2bfloat16(p0), h1 = __float2bfloat16(p1);
            __nv_bfloat16 h2 = __float2bfloat16(p2), h3 = __float2bfloat16(p3);
            __nv_bfloat16 e0 = __float2bfloat16(p0 - __bfloat162float(h0));
            __nv_bfloat16 e1 = __float2bfloat16(p1 - __bfloat162float(h1));
            __nv_bfloat16 e2 = __float2bfloat16(p2 - __bfloat162float(h2));
            __nv_bfloat16 e3 = __float2bfloat16(p3 - __bfloat162float(h3));
            uint32_t rowg = p0a + nt * 16;
            asm volatile("st.shared.b32 [%0], %1;" :: "r"(rowg),
                         "r"((uint32_t)(__bfloat16_as_ushort(h0)) |
                             ((uint32_t)__bfloat16_as_ushort(h1) << 16)) : "memory");
            asm volatile("st.shared.b32 [%0], %1;" :: "r"(rowg + 8 * 144),
                         "r"((uint32_t)(__bfloat16_as_ushort(h2)) |
                             ((uint32_t)__bfloat16_as_ushort(h3) << 16)) : "memory");
            asm volatile("st.shared.b32 [%0], %1;" :: "r"(rowg + (AQL - AQH)),
                         "r"((uint32_t)(__bfloat16_as_ushort(e0)) |
                             ((uint32_t)__bfloat16_as_ushort(e1) << 16)) : "memory");
            asm volatile("st.shared.b32 [%0], %1;" :: "r"(rowg + (AQL - AQH) + 8 * 144),
                         "r"((uint32_t)(__bfloat16_as_ushort(e2)) |
                             ((uint32_t)__bfloat16_as_ushort(e3) << 16)) : "memory");
        }
#pragma unroll
        for (int off = 1; off <= 2; off <<= 1) {
            lt0 += __shfl_xor_sync(0xffffffffu, lt0, off);
            lt1 += __shfl_xor_sync(0xffffffffu, lt1, off);
        }
        l0 = l0 * al0 + lt0;
        l1 = l1 * al1 + lt1;

#pragma unroll
        for (int nt = 0; nt < 8; nt++) {
            o[nt][0] *= al0;
            o[nt][1] *= al0;
            o[nt][2] *= al1;
            o[nt][3] *= al1;
        }
        __syncwarp();   // P rows are warp-private (stores -> ldmatrix)

        // O += P V (3-term bf16 split; V via trans ldmatrix)
#pragma unroll
        for (int kb = 0; kb < 4; kb++) {
            uint32_t ph[4], pl[4];
            LDSM_X4(ph[0], ph[1], ph[2], ph[3], sb + AQH + aoff + kb * 32);
            LDSM_X4(pl[0], pl[1], pl[2], pl[3], sb + AQL + aoff + kb * 32);
#pragma unroll
            for (int ng = 0; ng < 4; ng++) {
                uint32_t vd = stg + AVH_OFF + (kb * 16 + vRow) * 144 + ng * 32 + vC16;
                uint32_t vh0, vh1, vh2, vh3, vl0, vl1, vl2, vl3;
                LDSM_X4_T(vh0, vh1, vh2, vh3, vd);
                LDSM_X4_T(vl0, vl1, vl2, vl3, vd + AKL_OFF);
                float* d0 = o[ng * 2];
                float* d1 = o[ng * 2 + 1];
                MMA_BF16(d0, ph[0], ph[1], ph[2], ph[3], vh0, vh1);
                MMA_BF16(d0, pl[0], pl[1], pl[2], pl[3], vh0, vh1);
                MMA_BF16(d0, ph[0], ph[1], ph[2], ph[3], vl0, vl1);
                MMA_BF16(d1, ph[0], ph[1], ph[2], ph[3], vh2, vh3);
                MMA_BF16(d1, pl[0], pl[1], pl[2], pl[3], vh2, vh3);
                MMA_BF16(d1, ph[0], ph[1], ph[2], ph[3], vl2, vl3);
            }
        }
        __syncthreads();   // stage reuse 2 iters later
    }

    // normalize + fused bf16 hi/lo split store
    const float inv0 = 1.f / l0, inv1 = 1.f / l1;
    const int r0 = b * T_ + q0 + 16 * w + g;
#pragma unroll
    for (int nt = 0; nt < 8; nt++) {
        int col = h * HD_ + nt * 8 + 2 * q;
        float v00 = o[nt][0] * inv0, v01 = o[nt][1] * inv0;
        float v10 = o[nt][2] * inv1, v11 = o[nt][3] * inv1;
        __nv_bfloat16 h00 = __float2bfloat16(v00), h01 = __float2bfloat16(v01);
        __nv_bfloat16 h10 = __float2bfloat16(v10), h11 = __float2bfloat16(v11);
        __nv_bfloat16 l00 = __float2bfloat16(v00 - __bfloat162float(h00));
        __nv_bfloat16 l01 = __float2bfloat16(v01 - __bfloat162float(h01));
        __nv_bfloat16 l10 = __float2bfloat16(v10 - __bfloat162float(h10));
        __nv_bfloat16 l11 = __float2bfloat16(v11 - __bfloat162float(h11));
        *(__nv_bfloat162*)(yh + (size_t)r0 * C_ + col)       = __nv_bfloat162(h00, h01);
        *(__nv_bfloat162*)(yl + (size_t)r0 * C_ + col)       = __nv_bfloat162(l00, l01);
        *(__nv_bfloat162*)(yh + (size_t)(r0 + 8) * C_ + col) = __nv_bfloat162(h10, h11);
        *(__nv_bfloat162*)(yl + (size_t)(r0 + 8) * C_ + col) = __nv_bfloat162(l10, l11);
    }
}

extern "C" void kernel_launch(void* const* d_in, const int* in_sizes, int n_in,
                              void* d_out, int out_size)
{
    (void)in_sizes; (void)n_in; (void)out_size;
    const float* x      = (const float*)d_in[0];
    const float* W_attn = (const float*)d_in[1];
    const float* b_attn = (const float*)d_in[2];
    const float* W_proj = (const float*)d_in[3];
    const float* b_proj = (const float*)d_in[4];
    float* out = (float*)d_out;

    __nv_bfloat16 *qkvh, *qkvl, *xh, *xl, *wah, *wal, *wph, *wpl;
    cudaGetSymbolAddress((void**)&qkvh, g_qkvh);
    cudaGetSymbolAddress((void**)&qkvl, g_qkvl);
    cudaGetSymbolAddress((void**)&xh, g_xh);
    cudaGetSymbolAddress((void**)&xl, g_xl);
    cudaGetSymbolAddress((void**)&wah, g_wah);
    cudaGetSymbolAddress((void**)&wal, g_wal);
    cudaGetSymbolAddress((void**)&wph, g_wph);
    cudaGetSymbolAddress((void**)&wpl, g_wpl);

    cudaFuncSetAttribute(attn_mma, cudaFuncAttributeMaxDynamicSharedMemorySize, ATTN_SMEM);
    cudaFuncSetAttribute(gemm_mma<0>, cudaFuncAttributeMaxDynamicSharedMemorySize, GEMM_SMEM);
    cudaFuncSetAttribute(gemm_mma<1>, cudaFuncAttributeMaxDynamicSharedMemorySize, GEMM_SMEM);

    const int n4x = (BT * C_) / 4;

    split_k<<<(n4x + 255) / 256, 256>>>(x, xh, xl, n4x);
    tsplit_k<<<dim3(QKVC / 32, C_ / 32), dim3(32, 8)>>>(W_attn, wah, wal, C_, QKVC);
    tsplit_k<<<dim3(C_ / 32, C_ / 32), dim3(32, 8)>>>(W_proj, wph, wpl, C_, C_);

    // 1) qkv (bf16 hi/lo, Q cols pre-scaled by 1/8)
    gemm_mma<1><<<dim3(QKVC / GBN, BT / GBM), 256, GEMM_SMEM>>>(
        xh, xl, wah, wal, b_attn, nullptr, qkvh, qkvl, C_, BT, QKVC, C_);

    // 2) SDPA (bf16-split HMMA flash), writes split y into xh/xl
    attn_mma<<<dim3(T_ / 128, H_, B_), 256, ATTN_SMEM>>>(qkvh, qkvl, xh, xl);

    // 3) out = y @ W_proj + b_proj (fp32 out)
    gemm_mma<0><<<dim3(C_ / GBN, BT / GBM), 256, GEMM_SMEM>>>(
        xh, xl, wph, wpl, b_proj, out, nullptr, nullptr, 0, BT, C_, C_);
}